// round 5
// baseline (speedup 1.0000x reference)
#include <cuda_runtime.h>
#include <cstdint>

// InverseHaarUpsample: x [B, 4C, H, W] f32 -> out [B, C, 2H, 2W] f32
// B=16, C=64, H=W=128. Subband s at channel block s*C + c.
// Haar synthesis (filters /2), with a=LL, b=LH, c=HL, d=HH at (h, w):
//   out(2h+0, 2w+0) = (a - b - c + d)/2
//   out(2h+0, 2w+1) = (a - b + c - d)/2
//   out(2h+1, 2w+0) = (a + b - c - d)/2
//   out(2h+1, 2w+1) = (a + b + c + d)/2
//
// Each thread: 8 input floats per subband (2x float4 per stream, 8 LDG.128
// total -> MLP 8), emits 2x 64B per output row (8 STG.128 total).

namespace {
constexpr int C = 64;      // output channels
constexpr int H = 128;
constexpr int W = 128;
constexpr int WO = W / 8;                                // 16 input-pixel octets per row
constexpr long long SUB_STRIDE = (long long)C * H * W;   // elems between subbands
}

__device__ __forceinline__ void butterfly4(const float4& a, const float4& b,
                                           const float4& c, const float4& d,
                                           float4& top0, float4& top1,
                                           float4& bot0, float4& bot1) {
    float u0 = a.x - b.x, t0 = a.x + b.x, p0 = c.x - d.x, q0 = c.x + d.x;
    float u1 = a.y - b.y, t1 = a.y + b.y, p1 = c.y - d.y, q1 = c.y + d.y;
    float u2 = a.z - b.z, t2 = a.z + b.z, p2 = c.z - d.z, q2 = c.z + d.z;
    float u3 = a.w - b.w, t3 = a.w + b.w, p3 = c.w - d.w, q3 = c.w + d.w;
    top0 = make_float4(0.5f * (u0 - p0), 0.5f * (u0 + p0),
                       0.5f * (u1 - p1), 0.5f * (u1 + p1));
    top1 = make_float4(0.5f * (u2 - p2), 0.5f * (u2 + p2),
                       0.5f * (u3 - p3), 0.5f * (u3 + p3));
    bot0 = make_float4(0.5f * (t0 - q0), 0.5f * (t0 + q0),
                       0.5f * (t1 - q1), 0.5f * (t1 + q1));
    bot1 = make_float4(0.5f * (t2 - q2), 0.5f * (t2 + q2),
                       0.5f * (t3 - q3), 0.5f * (t3 + q3));
}

__global__ void __launch_bounds__(256)
inverse_haar_kernel(const float* __restrict__ x, float* __restrict__ out, int n_threads) {
    int n = blockIdx.x * blockDim.x + threadIdx.x;
    if (n >= n_threads) return;

    // n -> (b*C+c, h, wo); wo indexes octets of input columns
    int wo = n & (WO - 1);          // 0..15
    int h  = (n >> 4) & (H - 1);    // 0..127
    int bc = n >> 11;               // b*C + c
    int c  = bc & (C - 1);
    int b  = bc >> 6;

    // input base: ((b*4C + c)*H + h)*W + 8*wo   (32B aligned)
    long long ibase = (((long long)(b * (4 * C) + c) * H + h) * W) + (wo << 3);
    const float4* pa = reinterpret_cast<const float4*>(x + ibase);
    const float4* pb = reinterpret_cast<const float4*>(x + ibase + SUB_STRIDE);
    const float4* pc = reinterpret_cast<const float4*>(x + ibase + 2 * SUB_STRIDE);
    const float4* pd = reinterpret_cast<const float4*>(x + ibase + 3 * SUB_STRIDE);

    // 8 independent 16B loads issued back-to-back (MLP = 8)
    float4 a0 = pa[0], a1 = pa[1];
    float4 b0 = pb[0], b1 = pb[1];
    float4 c0 = pc[0], c1 = pc[1];
    float4 d0 = pd[0], d1 = pd[1];

    float4 t00, t01, bo0, bo1, t10, t11, bo2, bo3;
    butterfly4(a0, b0, c0, d0, t00, t01, bo0, bo1);
    butterfly4(a1, b1, c1, d1, t10, t11, bo2, bo3);

    // out base: ((b*C + c)*(2H) + 2h)*(2W) + 16*wo   (64B aligned)
    long long obase = (((long long)bc * (2 * H) + (h << 1)) * (2 * W)) + (wo << 4);
    float4* otop = reinterpret_cast<float4*>(out + obase);
    float4* obot = reinterpret_cast<float4*>(out + obase + 2 * W);
    otop[0] = t00; otop[1] = t01; otop[2] = t10; otop[3] = t11;
    obot[0] = bo0; obot[1] = bo1; obot[2] = bo2; obot[3] = bo3;
}

extern "C" void kernel_launch(void* const* d_in, const int* in_sizes, int n_in,
                              void* d_out, int out_size) {
    const float* x = (const float*)d_in[0];
    float* out = (float*)d_out;
    // Each thread handles 8 input pixels of one subband-group (32 output pixels).
    int n_threads = in_sizes[0] / 32;
    constexpr int threads = 256;
    int blocks = (n_threads + threads - 1) / threads;
    inverse_haar_kernel<<<blocks, threads>>>(x, out, n_threads);
}

// round 6
// speedup vs baseline: 1.0999x; 1.0999x over previous
#include <cuda_runtime.h>
#include <cstdint>

// InverseHaarUpsample: x [B, 4C, H, W] f32 -> out [B, C, 2H, 2W] f32
// B=16, C=64, H=W=128. Subband s at channel block s*C + c.
// Haar synthesis (filters /2), with a=LL, b=LH, c=HL, d=HH at (h, w):
//   out(2h+0, 2w+0) = (a - b - c + d)/2
//   out(2h+0, 2w+1) = (a - b + c - d)/2
//   out(2h+1, 2w+0) = (a + b - c - d)/2
//   out(2h+1, 2w+1) = (a + b + c + d)/2
//
// Proven-best structure (R3): per thread 4x LDG.128 (one per subband, MLP 4)
// + 4x STG.128 across two output rows. All 32-bit indexing (tensor fits in
// 2^31 elems) to cut 64-bit address IMADs.

namespace {
constexpr int C = 64;      // output channels
constexpr int H = 128;
constexpr int W = 128;
constexpr int WQ = W / 4;                            // 32 input-pixel quads per row
constexpr unsigned SUB_STRIDE = (unsigned)C * H * W; // elems between subbands
}

__global__ void __launch_bounds__(128)
inverse_haar_kernel(const float* __restrict__ x, float* __restrict__ out,
                    unsigned n_threads) {
    unsigned n = blockIdx.x * blockDim.x + threadIdx.x;
    if (n >= n_threads) return;

    // n -> (b*C+c, h, wq); wq indexes quads of input columns
    unsigned wq = n & (WQ - 1);          // 0..31
    unsigned h  = (n >> 5) & (H - 1);    // 0..127
    unsigned bc = n >> 12;               // b*C + c
    unsigned c  = bc & (C - 1);
    unsigned b  = bc >> 6;

    // input base: ((b*4C + c)*H + h)*W + 4*wq   (16B aligned)
    unsigned ibase = ((b * (4 * C) + c) * H + h) * W + (wq << 2);

    float4 va = *reinterpret_cast<const float4*>(x + ibase);                  // LL
    float4 vb = *reinterpret_cast<const float4*>(x + ibase + SUB_STRIDE);     // LH
    float4 vc = *reinterpret_cast<const float4*>(x + ibase + 2 * SUB_STRIDE); // HL
    float4 vd = *reinterpret_cast<const float4*>(x + ibase + 3 * SUB_STRIDE); // HH

    // butterfly per input pixel
    float u0 = va.x - vb.x, t0 = va.x + vb.x, p0 = vc.x - vd.x, q0 = vc.x + vd.x;
    float u1 = va.y - vb.y, t1 = va.y + vb.y, p1 = vc.y - vd.y, q1 = vc.y + vd.y;
    float u2 = va.z - vb.z, t2 = va.z + vb.z, p2 = vc.z - vd.z, q2 = vc.z + vd.z;
    float u3 = va.w - vb.w, t3 = va.w + vb.w, p3 = vc.w - vd.w, q3 = vc.w + vd.w;

    float4 top0 = make_float4(0.5f * (u0 - p0), 0.5f * (u0 + p0),
                              0.5f * (u1 - p1), 0.5f * (u1 + p1));
    float4 top1 = make_float4(0.5f * (u2 - p2), 0.5f * (u2 + p2),
                              0.5f * (u3 - p3), 0.5f * (u3 + p3));
    float4 bot0 = make_float4(0.5f * (t0 - q0), 0.5f * (t0 + q0),
                              0.5f * (t1 - q1), 0.5f * (t1 + q1));
    float4 bot1 = make_float4(0.5f * (t2 - q2), 0.5f * (t2 + q2),
                              0.5f * (t3 - q3), 0.5f * (t3 + q3));

    // out base: ((b*C + c)*(2H) + 2h)*(2W) + 8*wq   (32B aligned)
    unsigned obase = (bc * (2 * H) + (h << 1)) * (2 * W) + (wq << 3);
    *reinterpret_cast<float4*>(out + obase)             = top0;
    *reinterpret_cast<float4*>(out + obase + 4)         = top1;
    *reinterpret_cast<float4*>(out + obase + 2 * W)     = bot0;
    *reinterpret_cast<float4*>(out + obase + 2 * W + 4) = bot1;
}

extern "C" void kernel_launch(void* const* d_in, const int* in_sizes, int n_in,
                              void* d_out, int out_size) {
    const float* x = (const float*)d_in[0];
    float* out = (float*)d_out;
    // Each thread handles 4 input pixels of one subband-group (16 output pixels).
    unsigned n_threads = (unsigned)(in_sizes[0] / 16);
    constexpr int threads = 128;
    unsigned blocks = (n_threads + threads - 1) / threads;  // 32768
    inverse_haar_kernel<<<blocks, threads>>>(x, out, n_threads);
}